// round 15
// baseline (speedup 1.0000x reference)
#include <cuda_runtime.h>
#include <math.h>

// ---------------- problem constants ----------------
#define EDIM   768
#define NHEAD  12
#define HDIM   64
#define TLEN   512
#define BATCH  2
#define NTOK   1024           // B*T
#define PDIM   4
#define VDIM   256
#define PV     1024           // P*V

// ---------------- scratch (device globals; no allocation) ----------------
__device__ float g_x     [NTOK*EDIM];
__device__ float g_x0    [NTOK*EDIM];
__device__ float g_h     [NTOK*EDIM];
__device__ float g_qkv   [NTOK*3*EDIM];
__device__ float g_ff    [NTOK*4*EDIM];
__device__ float g_logits[NTOK*PV];
__device__ float g_sah   [NTOK*PDIM*VDIM];
__device__ float g_saqkv [NTOK*PDIM*3*EDIM];
__device__ float g_saattn[NTOK*EDIM];
__device__ float g_sax   [NTOK*VDIM];
__device__ float g_saff  [NTOK*4*VDIM];
__device__ float g_cos   [TLEN*32];
__device__ float g_sin   [TLEN*32];

// ---------------- rope tables (double trig for robustness) ----------------
__global__ void rope_table_kernel() {
    int t = blockIdx.x;
    int d = threadIdx.x;          // 0..31
    double inv = exp(-((double)(2*d) / 64.0) * log(10000.0));
    double f = (double)t * inv;
    g_cos[t*32 + d] = (float)cos(f);
    g_sin[t*32 + d] = (float)sin(f);
}

// ---------------- embedding gather: x0 = emb[tok]; x = x0 ----------------
__global__ void embed_kernel(const int* __restrict__ tokens,
                             const float* __restrict__ emb) {
    int row = blockIdx.x;                // token index 0..1023
    int tid = threadIdx.x;               // 256
    int tok = tokens[row];
    #pragma unroll
    for (int i = 0; i < 3; i++) {
        int c = tid + i*256;
        float v = emb[tok*EDIM + c];
        g_x0[row*EDIM + c] = v;
        g_x [row*EDIM + c] = v;
    }
}

// ---------------- LayerNorm (optional fused residual input) ----------------
// out[row] = LN(in[row] (+ res[row])) * g + b
__global__ void ln_kernel(const float* __restrict__ in,
                          const float* __restrict__ res,
                          const float* __restrict__ gamma,
                          const float* __restrict__ beta,
                          float* __restrict__ out, int cols) {
    int row = blockIdx.x;
    int tid = threadIdx.x;               // 256
    __shared__ float red[256];
    int nv = cols >> 8;                  // 1 or 3
    float v[3];
    float sum = 0.f;
    const float* ip = in + (size_t)row * cols;
    const float* rp = res ? res + (size_t)row * cols : nullptr;
    for (int i = 0; i < nv; i++) {
        int c = tid + i*256;
        float t = ip[c];
        if (rp) t += rp[c];
        v[i] = t;
        sum += t;
    }
    red[tid] = sum; __syncthreads();
    for (int o = 128; o > 0; o >>= 1) {
        if (tid < o) red[tid] += red[tid + o];
        __syncthreads();
    }
    float mean = red[0] / (float)cols;
    __syncthreads();
    float sq = 0.f;
    for (int i = 0; i < nv; i++) { float d = v[i] - mean; sq += d*d; }
    red[tid] = sq; __syncthreads();
    for (int o = 128; o > 0; o >>= 1) {
        if (tid < o) red[tid] += red[tid + o];
        __syncthreads();
    }
    float var = red[0] / (float)cols;
    float rs = rsqrtf(var + 1e-5f);
    float* op = out + (size_t)row * cols;
    for (int i = 0; i < nv; i++) {
        int c = tid + i*256;
        op[c] = (v[i] - mean) * rs * gamma[c] + beta[c];
    }
}

// ---------------- SGEMM: C = A(MxK) * B(KxN) [+bias][gelu][+res] ----------
// Requires: M%128==0, N%64==0, K%16==0 (true for all calls).
#define BM 128
#define BN 64
#define BK 16

__device__ __forceinline__ float gelu_exact(float x) {
    return 0.5f * x * (1.f + erff(x * 0.70710678118654752f));
}

__global__ __launch_bounds__(256)
void sgemm_kernel(const float* __restrict__ A, const float* __restrict__ B,
                  const float* __restrict__ bias, const float* __restrict__ res,
                  float* __restrict__ C,
                  int M, int N, int K, int res_stride, int mode) {
    __shared__ float As[BK][BM];
    __shared__ float Bs[BK][BN];
    int tid = threadIdx.x;
    int bm = blockIdx.y * BM;
    int bn = blockIdx.x * BN;
    int ty = tid >> 4;            // 0..15 -> 8 rows each
    int tx = tid & 15;            // 0..15 -> 4 cols each

    float acc[8][4];
    #pragma unroll
    for (int i = 0; i < 8; i++)
        #pragma unroll
        for (int j = 0; j < 4; j++) acc[i][j] = 0.f;

    int a_m  = tid & 63;          // row within 64-row half
    int a_k4 = tid >> 6;          // 0..3  (k group of 4)
    int b_k  = tid >> 4;          // 0..15
    int b_n4 = (tid & 15) * 4;

    const float* Ap0 = A + (size_t)(bm + a_m)      * K + a_k4*4;
    const float* Ap1 = A + (size_t)(bm + a_m + 64) * K + a_k4*4;

    for (int k0 = 0; k0 < K; k0 += BK) {
        float4 av0 = *(const float4*)(Ap0 + k0);
        float4 av1 = *(const float4*)(Ap1 + k0);
        As[a_k4*4+0][a_m]    = av0.x;
        As[a_k4*4+1][a_m]    = av0.y;
        As[a_k4*4+2][a_m]    = av0.z;
        As[a_k4*4+3][a_m]    = av0.w;
        As[a_k4*4+0][a_m+64] = av1.x;
        As[a_k4*4+1][a_m+64] = av1.y;
        As[a_k4*4+2][a_m+64] = av1.z;
        As[a_k4*4+3][a_m+64] = av1.w;
        float4 bv = *(const float4*)(B + (size_t)(k0 + b_k) * N + bn + b_n4);
        *(float4*)&Bs[b_k][b_n4] = bv;
        __syncthreads();
        #pragma unroll
        for (int k = 0; k < BK; k++) {
            float4 ra0 = *(const float4*)&As[k][ty*8];
            float4 ra1 = *(const float4*)&As[k][ty*8 + 4];
            float4 rb  = *(const float4*)&Bs[k][tx*4];
            float ra[8] = {ra0.x, ra0.y, ra0.z, ra0.w, ra1.x, ra1.y, ra1.z, ra1.w};
            float rbv[4] = {rb.x, rb.y, rb.z, rb.w};
            #pragma unroll
            for (int i = 0; i < 8; i++)
                #pragma unroll
                for (int j = 0; j < 4; j++)
                    acc[i][j] += ra[i] * rbv[j];
        }
        __syncthreads();
    }

    #pragma unroll
    for (int i = 0; i < 8; i++) {
        int m = bm + ty*8 + i;
        #pragma unroll
        for (int j = 0; j < 4; j++) {
            int n = bn + tx*4 + j;
            float v = acc[i][j];
            if (mode & 1) v += bias[n];
            if (mode & 2) v = gelu_exact(v);
            if (mode & 4) v += res[(size_t)m * res_stride + n];
            C[(size_t)m * N + n] = v;
        }
    }
}

// ---------------- patch attention (sliding window S), fused residual -----
// grid: (T, B*NH), 128 threads. x += attn_out
__global__ void patch_attn_kernel(const float* __restrict__ qkv,
                                  float* __restrict__ x, int S) {
    int j  = blockIdx.x;                 // query position
    int bh = blockIdx.y;
    int b  = bh / NHEAD, h = bh % NHEAD;
    int tid = threadIdx.x;               // 128
    __shared__ float qs[HDIM];
    __shared__ float sc[128];
    __shared__ float red[128];

    int lo = j - S + 1; if (lo < 0) lo = 0;
    int nk = j - lo + 1;                 // 1..S (<=128)

    const float* qrow = qkv + (size_t)(b*TLEN + j)*3*EDIM + h*HDIM;
    if (tid < 32) {
        float c = g_cos[j*32 + tid], s = g_sin[j*32 + tid];
        float x1 = qrow[tid], x2 = qrow[tid + 32];
        qs[tid]      = x1*c - x2*s;
        qs[tid + 32] = x1*s + x2*c;
    }
    __syncthreads();

    float score = -INFINITY;
    if (tid < nk) {
        int kk = lo + tid;
        const float* krow = qkv + (size_t)(b*TLEN + kk)*3*EDIM + EDIM + h*HDIM;
        float dot = 0.f;
        #pragma unroll 8
        for (int d = 0; d < 32; d++) {
            float c = g_cos[kk*32 + d], s = g_sin[kk*32 + d];
            float k1 = krow[d], k2 = krow[d + 32];
            dot += (k1*c - k2*s) * qs[d] + (k1*s + k2*c) * qs[d + 32];
        }
        score = dot * 0.125f;
    }
    sc[tid] = score;
    red[tid] = score;
    __syncthreads();
    for (int o = 64; o > 0; o >>= 1) {
        if (tid < o) red[tid] = fmaxf(red[tid], red[tid + o]);
        __syncthreads();
    }
    float mx = red[0];
    __syncthreads();
    float e = (tid < nk) ? expf(sc[tid] - mx) : 0.f;
    red[tid] = e;
    __syncthreads();
    for (int o = 64; o > 0; o >>= 1) {
        if (tid < o) red[tid] += red[tid + o];
        __syncthreads();
    }
    float denom = red[0];
    __syncthreads();
    sc[tid] = e / denom;
    __syncthreads();

    if (tid < HDIM) {
        const float* vbase = qkv + (size_t)(b*TLEN + lo)*3*EDIM + 2*EDIM + h*HDIM + tid;
        float accv = 0.f;
        for (int t = 0; t < nk; t++)
            accv += sc[t] * vbase[(size_t)t * 3*EDIM];
        x[(size_t)(b*TLEN + j)*EDIM + h*HDIM + tid] += accv;
    }
}

// ---------------- sa-block attention (P=4, query p=0 only) ---------------
// grid: NTOK blocks, 384 threads (12 warps = 12 heads)
__global__ void sa_attn_kernel(const float* __restrict__ saqkv,
                               float* __restrict__ out) {
    int token = blockIdx.x;
    int h    = threadIdx.x >> 5;         // head
    int lane = threadIdx.x & 31;
    const float* base = saqkv + (size_t)token * PDIM * 3*EDIM;

    // q at p=0 (rope at position 0 is identity)
    float q1 = base[h*HDIM + lane];
    float q2 = base[h*HDIM + lane + 32];

    float s[PDIM];
    #pragma unroll
    for (int p = 0; p < PDIM; p++) {
        const float* krow = base + (size_t)p*3*EDIM + EDIM + h*HDIM;
        float c = g_cos[p*32 + lane], sn = g_sin[p*32 + lane];
        float k1 = krow[lane], k2 = krow[lane + 32];
        float kr1 = k1*c - k2*sn;
        float kr2 = k1*sn + k2*c;
        float part = q1*kr1 + q2*kr2;
        #pragma unroll
        for (int o = 16; o > 0; o >>= 1)
            part += __shfl_xor_sync(0xffffffffu, part, o);
        s[p] = part * 0.125f;
    }
    float mx = fmaxf(fmaxf(s[0], s[1]), fmaxf(s[2], s[3]));
    float e[PDIM]; float den = 0.f;
    #pragma unroll
    for (int p = 0; p < PDIM; p++) { e[p] = expf(s[p] - mx); den += e[p]; }
    float o1 = 0.f, o2 = 0.f;
    #pragma unroll
    for (int p = 0; p < PDIM; p++) {
        const float* vrow = base + (size_t)p*3*EDIM + 2*EDIM + h*HDIM;
        float w = e[p] / den;
        o1 += w * vrow[lane];
        o2 += w * vrow[lane + 32];
    }
    out[(size_t)token*EDIM + h*HDIM + lane]      = o1;
    out[(size_t)token*EDIM + h*HDIM + lane + 32] = o2;
}

// ---------------- launch ----------------
static inline void run_gemm(const float* A, const float* B, const float* bias,
                            const float* res, float* C,
                            int M, int N, int K, int res_stride, int mode) {
    dim3 grid(N / BN, M / BM);
    sgemm_kernel<<<grid, 256>>>(A, B, bias, res, C, M, N, K, res_stride, mode);
}

extern "C" void kernel_launch(void* const* d_in, const int* in_sizes, int n_in,
                              void* d_out, int out_size) {
    const int*   tokens    = (const int*)  d_in[0];
    const float* emb       = (const float*)d_in[1];
    const float* ln0g      = (const float*)d_in[2];
    const float* ln0b      = (const float*)d_in[3];
    const float* ln1g      = (const float*)d_in[4];
    const float* ln1b      = (const float*)d_in[5];
    const float* qkv_w     = (const float*)d_in[6];
    const float* ff_w1     = (const float*)d_in[7];
    const float* ff_b1     = (const float*)d_in[8];
    const float* ff_w2     = (const float*)d_in[9];
    const float* ff_b2     = (const float*)d_in[10];
    const float* fin_g     = (const float*)d_in[11];
    const float* fin_b     = (const float*)d_in[12];
    const float* head_w    = (const float*)d_in[13];
    const float* head_b    = (const float*)d_in[14];
    const float* sa_ln0_g  = (const float*)d_in[15];
    const float* sa_ln0_b  = (const float*)d_in[16];
    const float* sa_ln1_g  = (const float*)d_in[17];
    const float* sa_ln1_b  = (const float*)d_in[18];
    const float* sa_qkv_w  = (const float*)d_in[19];
    const float* sa_proj_w = (const float*)d_in[20];
    const float* sa_proj_b = (const float*)d_in[21];
    const float* sa_ff_w1  = (const float*)d_in[22];
    const float* sa_ff_b1  = (const float*)d_in[23];
    const float* sa_ff_w2  = (const float*)d_in[24];
    const float* sa_ff_b2  = (const float*)d_in[25];
    float* out = (float*)d_out;

    float *x, *x0, *h, *qkv, *ff, *logits, *sah, *saqkv, *saattn, *sax, *saff;
    cudaGetSymbolAddress((void**)&x,      g_x);
    cudaGetSymbolAddress((void**)&x0,     g_x0);
    cudaGetSymbolAddress((void**)&h,      g_h);
    cudaGetSymbolAddress((void**)&qkv,    g_qkv);
    cudaGetSymbolAddress((void**)&ff,     g_ff);
    cudaGetSymbolAddress((void**)&logits, g_logits);
    cudaGetSymbolAddress((void**)&sah,    g_sah);
    cudaGetSymbolAddress((void**)&saqkv,  g_saqkv);
    cudaGetSymbolAddress((void**)&saattn, g_saattn);
    cudaGetSymbolAddress((void**)&sax,    g_sax);
    cudaGetSymbolAddress((void**)&saff,   g_saff);

    rope_table_kernel<<<TLEN, 32>>>();
    embed_kernel<<<NTOK, 256>>>(tokens, emb);

    for (int i = 0; i < 4; i++) {
        int S = 16 << i;
        // h = LN(x)
        ln_kernel<<<NTOK, 256>>>(x, nullptr, ln0g + i*EDIM, ln0b + i*EDIM, h, EDIM);
        // qkv = h @ qkv_w[i]
        run_gemm(h, qkv_w + (size_t)i*EDIM*3*EDIM, nullptr, nullptr, qkv,
                 NTOK, 3*EDIM, EDIM, 0, 0);
        // x += attn(qkv)
        {
            dim3 grid(TLEN, BATCH*NHEAD);
            patch_attn_kernel<<<grid, 128>>>(qkv, x, S);
        }
        // h = LN(x)
        ln_kernel<<<NTOK, 256>>>(x, nullptr, ln1g + i*EDIM, ln1b + i*EDIM, h, EDIM);
        // ff = gelu(h @ w1 + b1)
        run_gemm(h, ff_w1 + (size_t)i*EDIM*4*EDIM, ff_b1 + (size_t)i*4*EDIM,
                 nullptr, ff, NTOK, 4*EDIM, EDIM, 0, 1 | 2);
        // x = x + ff @ w2 + b2
        run_gemm(ff, ff_w2 + (size_t)i*4*EDIM*EDIM, ff_b2 + (size_t)i*EDIM,
                 x, x, NTOK, EDIM, 4*EDIM, EDIM, 1 | 4);
    }

    // h = LN(x0 + x)
    ln_kernel<<<NTOK, 256>>>(x, x0, fin_g, fin_b, h, EDIM);
    // logits = h @ head_w + head_b     (NTOK x 1024)
    run_gemm(h, head_w, head_b, nullptr, logits, NTOK, PV, EDIM, 0, 1);

    // sa block
    // sah = LN over V per (b,t,p): 4096 rows x 256
    ln_kernel<<<NTOK*PDIM, 256>>>(logits, nullptr, sa_ln0_g, sa_ln0_b, sah, VDIM);
    // saqkv = sah @ sa_qkv_w  (4096 x 2304)
    run_gemm(sah, sa_qkv_w, nullptr, nullptr, saqkv, NTOK*PDIM, 3*EDIM, VDIM, 0, 0);
    // attention over P=4, query p=0 only
    sa_attn_kernel<<<NTOK, 384>>>(saqkv, saattn);
    // sax = logits[:, p=0, :] + saattn @ sa_proj_w + sa_proj_b
    run_gemm(saattn, sa_proj_w, sa_proj_b, logits, sax, NTOK, VDIM, EDIM, PV, 1 | 4);
    // sah(reuse first 1024 rows) = LN(sax)
    ln_kernel<<<NTOK, 256>>>(sax, nullptr, sa_ln1_g, sa_ln1_b, sah, VDIM);
    // saff = gelu(sah @ sa_ff_w1 + b1)
    run_gemm(sah, sa_ff_w1, sa_ff_b1, nullptr, saff, NTOK, 4*VDIM, VDIM, 0, 1 | 2);
    // out = sax + saff @ sa_ff_w2 + b2
    run_gemm(saff, sa_ff_w2, sa_ff_b2, sax, out, NTOK, VDIM, 4*VDIM, VDIM, 1 | 4);
}

// round 16
// speedup vs baseline: 1.0012x; 1.0012x over previous
#include <cuda_runtime.h>
#include <math.h>

// ---------------- problem constants ----------------
#define EDIM   768
#define NHEAD  12
#define HDIM   64
#define TLEN   512
#define BATCH  2
#define NTOK   1024           // B*T
#define PDIM   4
#define VDIM   256
#define PV     1024           // P*V

// ---------------- scratch (device globals; no allocation) ----------------
__device__ float g_x     [NTOK*EDIM];
__device__ float g_x0    [NTOK*EDIM];
__device__ float g_h     [NTOK*EDIM];
__device__ float g_qkv   [NTOK*3*EDIM];
__device__ float g_ff    [NTOK*4*EDIM];
__device__ float g_logits[NTOK*PV];
__device__ float g_sah   [NTOK*PDIM*VDIM];
__device__ float g_saqkv [NTOK*PDIM*3*EDIM];
__device__ float g_saattn[NTOK*EDIM];
__device__ float g_sax   [NTOK*VDIM];
__device__ float g_saff  [NTOK*4*VDIM];
__device__ float g_cos   [TLEN*32];
__device__ float g_sin   [TLEN*32];

// ---------------- rope tables (double trig for robustness) ----------------
__global__ void rope_table_kernel() {
    int t = blockIdx.x;
    int d = threadIdx.x;          // 0..31
    double inv = exp(-((double)(2*d) / 64.0) * log(10000.0));
    double f = (double)t * inv;
    g_cos[t*32 + d] = (float)cos(f);
    g_sin[t*32 + d] = (float)sin(f);
}

// ---------------- embedding gather: x0 = emb[tok]; x = x0 ----------------
__global__ void embed_kernel(const int* __restrict__ tokens,
                             const float* __restrict__ emb) {
    int row = blockIdx.x;                // token index 0..1023
    int tid = threadIdx.x;               // 256
    int tok = tokens[row];
    #pragma unroll
    for (int i = 0; i < 3; i++) {
        int c = tid + i*256;
        float v = emb[tok*EDIM + c];
        g_x0[row*EDIM + c] = v;
        g_x [row*EDIM + c] = v;
    }
}

// ---------------- LayerNorm (optional fused residual input) ----------------
// out[row] = LN(in[row] (+ res[row])) * g + b
__global__ void ln_kernel(const float* __restrict__ in,
                          const float* __restrict__ res,
                          const float* __restrict__ gamma,
                          const float* __restrict__ beta,
                          float* __restrict__ out, int cols) {
    int row = blockIdx.x;
    int tid = threadIdx.x;               // 256
    __shared__ float red[256];
    int nv = cols >> 8;                  // 1 or 3
    float v[3];
    float sum = 0.f;
    const float* ip = in + (size_t)row * cols;
    const float* rp = res ? res + (size_t)row * cols : nullptr;
    for (int i = 0; i < nv; i++) {
        int c = tid + i*256;
        float t = ip[c];
        if (rp) t += rp[c];
        v[i] = t;
        sum += t;
    }
    red[tid] = sum; __syncthreads();
    for (int o = 128; o > 0; o >>= 1) {
        if (tid < o) red[tid] += red[tid + o];
        __syncthreads();
    }
    float mean = red[0] / (float)cols;
    __syncthreads();
    float sq = 0.f;
    for (int i = 0; i < nv; i++) { float d = v[i] - mean; sq += d*d; }
    red[tid] = sq; __syncthreads();
    for (int o = 128; o > 0; o >>= 1) {
        if (tid < o) red[tid] += red[tid + o];
        __syncthreads();
    }
    float var = red[0] / (float)cols;
    float rs = rsqrtf(var + 1e-5f);
    float* op = out + (size_t)row * cols;
    for (int i = 0; i < nv; i++) {
        int c = tid + i*256;
        op[c] = (v[i] - mean) * rs * gamma[c] + beta[c];
    }
}

// ---------------- SGEMM: C = A(MxK) * B(KxN) [+bias][gelu][+res] ----------
// Requires: M%128==0, N%64==0, K%16==0 (true for all calls).
#define BM 128
#define BN 64
#define BK 16

__device__ __forceinline__ float gelu_exact(float x) {
    return 0.5f * x * (1.f + erff(x * 0.70710678118654752f));
}

__global__ __launch_bounds__(256)
void sgemm_kernel(const float* __restrict__ A, const float* __restrict__ B,
                  const float* __restrict__ bias, const float* __restrict__ res,
                  float* __restrict__ C,
                  int M, int N, int K, int res_stride, int mode) {
    __shared__ float As[BK][BM];
    __shared__ float Bs[BK][BN];
    int tid = threadIdx.x;
    int bm = blockIdx.y * BM;
    int bn = blockIdx.x * BN;
    int ty = tid >> 4;            // 0..15 -> 8 rows each
    int tx = tid & 15;            // 0..15 -> 4 cols each

    float acc[8][4];
    #pragma unroll
    for (int i = 0; i < 8; i++)
        #pragma unroll
        for (int j = 0; j < 4; j++) acc[i][j] = 0.f;

    int a_m  = tid & 63;          // row within 64-row half
    int a_k4 = tid >> 6;          // 0..3  (k group of 4)
    int b_k  = tid >> 4;          // 0..15
    int b_n4 = (tid & 15) * 4;

    const float* Ap0 = A + (size_t)(bm + a_m)      * K + a_k4*4;
    const float* Ap1 = A + (size_t)(bm + a_m + 64) * K + a_k4*4;

    for (int k0 = 0; k0 < K; k0 += BK) {
        float4 av0 = *(const float4*)(Ap0 + k0);
        float4 av1 = *(const float4*)(Ap1 + k0);
        As[a_k4*4+0][a_m]    = av0.x;
        As[a_k4*4+1][a_m]    = av0.y;
        As[a_k4*4+2][a_m]    = av0.z;
        As[a_k4*4+3][a_m]    = av0.w;
        As[a_k4*4+0][a_m+64] = av1.x;
        As[a_k4*4+1][a_m+64] = av1.y;
        As[a_k4*4+2][a_m+64] = av1.z;
        As[a_k4*4+3][a_m+64] = av1.w;
        float4 bv = *(const float4*)(B + (size_t)(k0 + b_k) * N + bn + b_n4);
        *(float4*)&Bs[b_k][b_n4] = bv;
        __syncthreads();
        #pragma unroll
        for (int k = 0; k < BK; k++) {
            float4 ra0 = *(const float4*)&As[k][ty*8];
            float4 ra1 = *(const float4*)&As[k][ty*8 + 4];
            float4 rb  = *(const float4*)&Bs[k][tx*4];
            float ra[8] = {ra0.x, ra0.y, ra0.z, ra0.w, ra1.x, ra1.y, ra1.z, ra1.w};
            float rbv[4] = {rb.x, rb.y, rb.z, rb.w};
            #pragma unroll
            for (int i = 0; i < 8; i++)
                #pragma unroll
                for (int j = 0; j < 4; j++)
                    acc[i][j] += ra[i] * rbv[j];
        }
        __syncthreads();
    }

    #pragma unroll
    for (int i = 0; i < 8; i++) {
        int m = bm + ty*8 + i;
        #pragma unroll
        for (int j = 0; j < 4; j++) {
            int n = bn + tx*4 + j;
            float v = acc[i][j];
            if (mode & 1) v += bias[n];
            if (mode & 2) v = gelu_exact(v);
            if (mode & 4) v += res[(size_t)m * res_stride + n];
            C[(size_t)m * N + n] = v;
        }
    }
}

// ---------------- patch attention (sliding window S), fused residual -----
// grid: (T, B*NH), 128 threads. x += attn_out
__global__ void patch_attn_kernel(const float* __restrict__ qkv,
                                  float* __restrict__ x, int S) {
    int j  = blockIdx.x;                 // query position
    int bh = blockIdx.y;
    int b  = bh / NHEAD, h = bh % NHEAD;
    int tid = threadIdx.x;               // 128
    __shared__ float qs[HDIM];
    __shared__ float sc[128];
    __shared__ float red[128];

    int lo = j - S + 1; if (lo < 0) lo = 0;
    int nk = j - lo + 1;                 // 1..S (<=128)

    const float* qrow = qkv + (size_t)(b*TLEN + j)*3*EDIM + h*HDIM;
    if (tid < 32) {
        float c = g_cos[j*32 + tid], s = g_sin[j*32 + tid];
        float x1 = qrow[tid], x2 = qrow[tid + 32];
        qs[tid]      = x1*c - x2*s;
        qs[tid + 32] = x1*s + x2*c;
    }
    __syncthreads();

    float score = -INFINITY;
    if (tid < nk) {
        int kk = lo + tid;
        const float* krow = qkv + (size_t)(b*TLEN + kk)*3*EDIM + EDIM + h*HDIM;
        float dot = 0.f;
        #pragma unroll 8
        for (int d = 0; d < 32; d++) {
            float c = g_cos[kk*32 + d], s = g_sin[kk*32 + d];
            float k1 = krow[d], k2 = krow[d + 32];
            dot += (k1*c - k2*s) * qs[d] + (k1*s + k2*c) * qs[d + 32];
        }
        score = dot * 0.125f;
    }
    sc[tid] = score;
    red[tid] = score;
    __syncthreads();
    for (int o = 64; o > 0; o >>= 1) {
        if (tid < o) red[tid] = fmaxf(red[tid], red[tid + o]);
        __syncthreads();
    }
    float mx = red[0];
    __syncthreads();
    float e = (tid < nk) ? expf(sc[tid] - mx) : 0.f;
    red[tid] = e;
    __syncthreads();
    for (int o = 64; o > 0; o >>= 1) {
        if (tid < o) red[tid] += red[tid + o];
        __syncthreads();
    }
    float denom = red[0];
    __syncthreads();
    sc[tid] = e / denom;
    __syncthreads();

    if (tid < HDIM) {
        const float* vbase = qkv + (size_t)(b*TLEN + lo)*3*EDIM + 2*EDIM + h*HDIM + tid;
        float accv = 0.f;
        for (int t = 0; t < nk; t++)
            accv += sc[t] * vbase[(size_t)t * 3*EDIM];
        x[(size_t)(b*TLEN + j)*EDIM + h*HDIM + tid] += accv;
    }
}

// ---------------- sa-block attention (P=4, query p=0 only) ---------------
// grid: NTOK blocks, 384 threads (12 warps = 12 heads)
__global__ void sa_attn_kernel(const float* __restrict__ saqkv,
                               float* __restrict__ out) {
    int token = blockIdx.x;
    int h    = threadIdx.x >> 5;         // head
    int lane = threadIdx.x & 31;
    const float* base = saqkv + (size_t)token * PDIM * 3*EDIM;

    // q at p=0 (rope at position 0 is identity)
    float q1 = base[h*HDIM + lane];
    float q2 = base[h*HDIM + lane + 32];

    float s[PDIM];
    #pragma unroll
    for (int p = 0; p < PDIM; p++) {
        const float* krow = base + (size_t)p*3*EDIM + EDIM + h*HDIM;
        float c = g_cos[p*32 + lane], sn = g_sin[p*32 + lane];
        float k1 = krow[lane], k2 = krow[lane + 32];
        float kr1 = k1*c - k2*sn;
        float kr2 = k1*sn + k2*c;
        float part = q1*kr1 + q2*kr2;
        #pragma unroll
        for (int o = 16; o > 0; o >>= 1)
            part += __shfl_xor_sync(0xffffffffu, part, o);
        s[p] = part * 0.125f;
    }
    float mx = fmaxf(fmaxf(s[0], s[1]), fmaxf(s[2], s[3]));
    float e[PDIM]; float den = 0.f;
    #pragma unroll
    for (int p = 0; p < PDIM; p++) { e[p] = expf(s[p] - mx); den += e[p]; }
    float o1 = 0.f, o2 = 0.f;
    #pragma unroll
    for (int p = 0; p < PDIM; p++) {
        const float* vrow = base + (size_t)p*3*EDIM + 2*EDIM + h*HDIM;
        float w = e[p] / den;
        o1 += w * vrow[lane];
        o2 += w * vrow[lane + 32];
    }
    out[(size_t)token*EDIM + h*HDIM + lane]      = o1;
    out[(size_t)token*EDIM + h*HDIM + lane + 32] = o2;
}

// ---------------- launch ----------------
static inline void run_gemm(const float* A, const float* B, const float* bias,
                            const float* res, float* C,
                            int M, int N, int K, int res_stride, int mode) {
    dim3 grid(N / BN, M / BM);
    sgemm_kernel<<<grid, 256>>>(A, B, bias, res, C, M, N, K, res_stride, mode);
}

extern "C" void kernel_launch(void* const* d_in, const int* in_sizes, int n_in,
                              void* d_out, int out_size) {
    const int*   tokens    = (const int*)  d_in[0];
    const float* emb       = (const float*)d_in[1];
    const float* ln0g      = (const float*)d_in[2];
    const float* ln0b      = (const float*)d_in[3];
    const float* ln1g      = (const float*)d_in[4];
    const float* ln1b      = (const float*)d_in[5];
    const float* qkv_w     = (const float*)d_in[6];
    const float* ff_w1     = (const float*)d_in[7];
    const float* ff_b1     = (const float*)d_in[8];
    const float* ff_w2     = (const float*)d_in[9];
    const float* ff_b2     = (const float*)d_in[10];
    const float* fin_g     = (const float*)d_in[11];
    const float* fin_b     = (const float*)d_in[12];
    const float* head_w    = (const float*)d_in[13];
    const float* head_b    = (const float*)d_in[14];
    const float* sa_ln0_g  = (const float*)d_in[15];
    const float* sa_ln0_b  = (const float*)d_in[16];
    const float* sa_ln1_g  = (const float*)d_in[17];
    const float* sa_ln1_b  = (const float*)d_in[18];
    const float* sa_qkv_w  = (const float*)d_in[19];
    const float* sa_proj_w = (const float*)d_in[20];
    const float* sa_proj_b = (const float*)d_in[21];
    const float* sa_ff_w1  = (const float*)d_in[22];
    const float* sa_ff_b1  = (const float*)d_in[23];
    const float* sa_ff_w2  = (const float*)d_in[24];
    const float* sa_ff_b2  = (const float*)d_in[25];
    float* out = (float*)d_out;

    float *x, *x0, *h, *qkv, *ff, *logits, *sah, *saqkv, *saattn, *sax, *saff;
    cudaGetSymbolAddress((void**)&x,      g_x);
    cudaGetSymbolAddress((void**)&x0,     g_x0);
    cudaGetSymbolAddress((void**)&h,      g_h);
    cudaGetSymbolAddress((void**)&qkv,    g_qkv);
    cudaGetSymbolAddress((void**)&ff,     g_ff);
    cudaGetSymbolAddress((void**)&logits, g_logits);
    cudaGetSymbolAddress((void**)&sah,    g_sah);
    cudaGetSymbolAddress((void**)&saqkv,  g_saqkv);
    cudaGetSymbolAddress((void**)&saattn, g_saattn);
    cudaGetSymbolAddress((void**)&sax,    g_sax);
    cudaGetSymbolAddress((void**)&saff,   g_saff);

    rope_table_kernel<<<TLEN, 32>>>();
    embed_kernel<<<NTOK, 256>>>(tokens, emb);

    for (int i = 0; i < 4; i++) {
        int S = 16 << i;
        // h = LN(x)
        ln_kernel<<<NTOK, 256>>>(x, nullptr, ln0g + i*EDIM, ln0b + i*EDIM, h, EDIM);
        // qkv = h @ qkv_w[i]
        run_gemm(h, qkv_w + (size_t)i*EDIM*3*EDIM, nullptr, nullptr, qkv,
                 NTOK, 3*EDIM, EDIM, 0, 0);
        // x += attn(qkv)
        {
            dim3 grid(TLEN, BATCH*NHEAD);
            patch_attn_kernel<<<grid, 128>>>(qkv, x, S);
        }
        // h = LN(x)
        ln_kernel<<<NTOK, 256>>>(x, nullptr, ln1g + i*EDIM, ln1b + i*EDIM, h, EDIM);
        // ff = gelu(h @ w1 + b1)
        run_gemm(h, ff_w1 + (size_t)i*EDIM*4*EDIM, ff_b1 + (size_t)i*4*EDIM,
                 nullptr, ff, NTOK, 4*EDIM, EDIM, 0, 1 | 2);
        // x = x + ff @ w2 + b2
        run_gemm(ff, ff_w2 + (size_t)i*4*EDIM*EDIM, ff_b2 + (size_t)i*EDIM,
                 x, x, NTOK, EDIM, 4*EDIM, EDIM, 1 | 4);
    }

    // h = LN(x0 + x)
    ln_kernel<<<NTOK, 256>>>(x, x0, fin_g, fin_b, h, EDIM);
    // logits = h @ head_w + head_b     (NTOK x 1024)
    run_gemm(h, head_w, head_b, nullptr, logits, NTOK, PV, EDIM, 0, 1);

    // sa block
    // sah = LN over V per (b,t,p): 4096 rows x 256
    ln_kernel<<<NTOK*PDIM, 256>>>(logits, nullptr, sa_ln0_g, sa_ln0_b, sah, VDIM);
    // saqkv = sah @ sa_qkv_w  (4096 x 2304)
    run_gemm(sah, sa_qkv_w, nullptr, nullptr, saqkv, NTOK*PDIM, 3*EDIM, VDIM, 0, 0);
    // attention over P=4, query p=0 only
    sa_attn_kernel<<<NTOK, 384>>>(saqkv, saattn);
    // sax = logits[:, p=0, :] + saattn @ sa_proj_w + sa_proj_b
    run_gemm(saattn, sa_proj_w, sa_proj_b, logits, sax, NTOK, VDIM, EDIM, PV, 1 | 4);
    // sah(reuse first 1024 rows) = LN(sax)
    ln_kernel<<<NTOK, 256>>>(sax, nullptr, sa_ln1_g, sa_ln1_b, sah, VDIM);
    // saff = gelu(sah @ sa_ff_w1 + b1)
    run_gemm(sah, sa_ff_w1, sa_ff_b1, nullptr, saff, NTOK, 4*VDIM, VDIM, 0, 1 | 2);
    // out = sax + saff @ sa_ff_w2 + b2
    run_gemm(saff, sa_ff_w2, sa_ff_b2, sax, out, NTOK, VDIM, 4*VDIM, VDIM, 1 | 4);
}